// round 7
// baseline (speedup 1.0000x reference)
#include <cuda_runtime.h>
#include <cuda_fp16.h>
#include <cstdint>

#define H 128
#define MAX_SOTU 100000
#define MAX_TAXON 50000

// Scratch: factored first-layer outputs, stored fp16 (halves edge-pass traffic).
__device__ __half gUh[(size_t)MAX_SOTU * H];   // 25.6 MB
__device__ __half gVh[(size_t)MAX_TAXON * H];  // 12.8 MB
// Pre-swizzled fp16 hi/lo SMEM images of the two W1 halves, layout [n][k] with
// XOR swizzle (2k)^((n&7)<<4) on the byte offset within each 256B row.
__device__ __align__(16) unsigned short gBhi[2][128 * 128];
__device__ __align__(16) unsigned short gBlo[2][128 * 128];

__device__ __forceinline__ uint32_t smem_u32(const void* p) {
    uint32_t a;
    asm("{ .reg .u64 t; cvta.to.shared.u64 t, %1; cvt.u32.u64 %0, t; }" : "=r"(a) : "l"(p));
    return a;
}
__device__ __forceinline__ void ldsm4(uint32_t& r0, uint32_t& r1, uint32_t& r2,
                                      uint32_t& r3, uint32_t addr) {
    asm volatile("ldmatrix.sync.aligned.m8n8.x4.shared.b16 {%0,%1,%2,%3}, [%4];"
                 : "=r"(r0), "=r"(r1), "=r"(r2), "=r"(r3) : "r"(addr));
}
__device__ __forceinline__ void mma16816(float* c, const uint32_t* a, const uint32_t* b) {
    asm volatile(
        "mma.sync.aligned.m16n8k16.row.col.f32.f16.f16.f32 "
        "{%0,%1,%2,%3}, {%4,%5,%6,%7}, {%8,%9}, {%0,%1,%2,%3};"
        : "+f"(c[0]), "+f"(c[1]), "+f"(c[2]), "+f"(c[3])
        : "r"(a[0]), "r"(a[1]), "r"(a[2]), "r"(a[3]), "r"(b[0]), "r"(b[1]));
}
__device__ __forceinline__ void cp16(uint32_t dst, const void* src) {
    asm volatile("cp.async.cg.shared.global [%0], [%1], 16;" :: "r"(dst), "l"(src));
}
#define CP_COMMIT() asm volatile("cp.async.commit_group;" ::: "memory")
#define CP_WAIT0()  asm volatile("cp.async.wait_group 0;" ::: "memory")

__device__ __forceinline__ unsigned short h_bits(__half h) {
    return *reinterpret_cast<unsigned short*>(&h);
}
// Byte offset of element (r, k) in a 128-wide fp16 tile: 256B rows, XOR swizzle.
__device__ __forceinline__ uint32_t swz(int r, int k) {
    return (uint32_t)(r * 256 + ((k * 2) ^ ((r & 7) << 4)));
}

// ---------------- Prep: W1 halves -> pre-swizzled fp16 hi/lo images ----------------
__global__ void prep_w_kernel(const float* __restrict__ w1) {
    int stride = gridDim.x * blockDim.x;
    for (int idx = blockIdx.x * blockDim.x + threadIdx.x; idx < 2 * 128 * 128; idx += stride) {
        int half_id = idx >> 14;
        int e = idx & 16383;
        int o = e >> 7, k = e & 127;   // o = output col (n), k = input channel
        float x = w1[o * 256 + half_id * 128 + k];
        __half h = __float2half_rn(x);
        __half l = __float2half_rn(x - __half2float(h));
        uint32_t sw = swz(o, k) >> 1;
        gBhi[half_id][sw] = h_bits(h);
        gBlo[half_id][sw] = h_bits(l);
    }
}

// ---------------- Persistent first layer on HMMA: Out = Z @ W1half^T (+b1) ----------------
// Grid = NCTA persistent CTAs. CTAs [0, gU) stride over U tiles, rest over V tiles.
// Per CTA: B hi/lo loaded once; loop over 64-row tiles with software pipeline:
//   LDG A(t+1) -> regs | MMA(t) from smem | convert+STS A(t+1) | staged fp16 epilogue(t).
// SMEM: Bhi 32K | Blo 32K | A buf0 16K | A buf1 16K | sOut 16K = 112 KB.
__global__ void __launch_bounds__(256, 1)
mlp_mma_kernel(const float* __restrict__ zU, const float* __restrict__ zV,
               const float* __restrict__ b1,
               __half* __restrict__ outU, __half* __restrict__ outV,
               int nU, int nV, int gU_ctas, int gV_ctas)
{
    extern __shared__ char raw[];
    char* base = (char*)(((uintptr_t)raw + 255) & ~(uintptr_t)255);
    const uint32_t sb = smem_u32(base);
    const uint32_t offBhi = 0, offBlo = 32 * 1024;
    const uint32_t offA[2] = { 64u * 1024u, 80u * 1024u };
    char* sOut = base + 96 * 1024;

    const int tid = threadIdx.x;
    const int bx = blockIdx.x;

    const float* Z;
    __half* Out;
    int nrows, half_id, addBias, nCtas, ctaIdx;
    if (bx < gU_ctas) {
        Z = zU; Out = outU; nrows = nU; half_id = 0; addBias = 1;
        nCtas = gU_ctas; ctaIdx = bx;
    } else {
        Z = zV; Out = outV; nrows = nV; half_id = 1; addBias = 0;
        nCtas = gV_ctas; ctaIdx = bx - gU_ctas;
    }
    const int nTiles = (nrows + 63) / 64;

    // B tiles via cp.async, once per CTA.
    {
        const char* bh = reinterpret_cast<const char*>(gBhi[half_id]);
        const char* bl = reinterpret_cast<const char*>(gBlo[half_id]);
        #pragma unroll
        for (int i = 0; i < 8; i++) {
            int off = (tid + i * 256) * 16;
            cp16(sb + offBhi + off, bh + off);
            cp16(sb + offBlo + off, bl + off);
        }
        CP_COMMIT();
    }

    // Per-thread A-tile element coords: 8 float4 quads (64 rows x 32 quads / 256 thr).
    int a_r[8], a_kq[8];
    #pragma unroll
    for (int j = 0; j < 8; j++) {
        int i = tid + j * 256;
        a_r[j] = i >> 5; a_kq[j] = i & 31;
    }

    float4 vreg[8];
    auto ldgA = [&](int r0) {
        #pragma unroll
        for (int j = 0; j < 8; j++) {
            int rr = r0 + a_r[j];
            vreg[j] = (rr < nrows)
                ? *reinterpret_cast<const float4*>(&Z[(size_t)rr * H + a_kq[j] * 4])
                : make_float4(0.f, 0.f, 0.f, 0.f);
        }
    };
    auto stsA = [&](uint32_t bufOff) {
        #pragma unroll
        for (int j = 0; j < 8; j++) {
            uint32_t sw = swz(a_r[j], a_kq[j] * 4);
            char* p = base + bufOff + sw;
            *reinterpret_cast<__half2*>(p)     = __floats2half2_rn(vreg[j].x, vreg[j].y);
            *reinterpret_cast<__half2*>(p + 4) = __floats2half2_rn(vreg[j].z, vreg[j].w);
        }
    };

    const int w = tid >> 5, lane = tid & 31;
    const int mb = (w & 3) * 16;     // warp M origin
    const int nb = (w >> 2) * 64;    // warp N origin
    const int a_row = mb + (lane & 15);
    const int a_kof = (lane >> 4) * 8;
    const int b_row = nb + (lane >> 4) * 8 + (lane & 7);
    const int b_kof = ((lane >> 3) & 1) * 8;
    const int g = lane >> 2, q = lane & 3;

    float2 bv[8];
    #pragma unroll
    for (int ni = 0; ni < 8; ni++) {
        int col = nb + ni * 8 + 2 * q;
        bv[ni] = addBias ? *reinterpret_cast<const float2*>(&b1[col])
                         : make_float2(0.f, 0.f);
    }

    // Preload first tile.
    int t = ctaIdx;
    if (t >= nTiles) { CP_WAIT0(); return; }
    ldgA(t * 64);
    stsA(offA[0]);
    CP_WAIT0();
    __syncthreads();

    int bufc = 0;
    for (; t < nTiles; t += nCtas, bufc ^= 1) {
        const int tn = t + nCtas;
        const bool hasNext = tn < nTiles;
        if (hasNext) ldgA(tn * 64);

        float acc[8][4];
        #pragma unroll
        for (int ni = 0; ni < 8; ni++)
            #pragma unroll
            for (int qq = 0; qq < 4; qq++) acc[ni][qq] = 0.f;

        // 16 iters = 2 passes (Bhi, Blo) x 8 k-steps, fragment double-buffered.
        const uint32_t Abase = sb + offA[bufc];
        uint32_t a[2][4], b[2][8][2];
        auto load_frags = [&](int buf, int it) {
            int pass = it >> 3, k0 = (it & 7) * 16;
            uint32_t Bbase = sb + (pass ? offBlo : offBhi);
            ldsm4(a[buf][0], a[buf][1], a[buf][2], a[buf][3],
                  Abase + swz(a_row, k0 + a_kof));
            #pragma unroll
            for (int nj = 0; nj < 4; nj++)
                ldsm4(b[buf][2 * nj][0], b[buf][2 * nj][1],
                      b[buf][2 * nj + 1][0], b[buf][2 * nj + 1][1],
                      Bbase + swz(b_row + nj * 16, k0 + b_kof));
        };
        load_frags(0, 0);
        #pragma unroll
        for (int it = 0; it < 16; it++) {
            int cur = it & 1;
            if (it < 15) load_frags(cur ^ 1, it + 1);
            #pragma unroll
            for (int ni = 0; ni < 8; ni++)
                mma16816(acc[ni], a[cur], b[cur][ni]);
        }

        if (hasNext) stsA(offA[bufc ^ 1]);

        // Epilogue: acc -> sOut (swizzled fp16), then coalesced uint4 stores.
        __syncthreads();   // prior STG reads of sOut done; STS of next A visible next iter
        #pragma unroll
        for (int hm = 0; hm < 2; hm++) {
            int row = mb + hm * 8 + g;
            #pragma unroll
            for (int ni = 0; ni < 8; ni++) {
                int col = nb + ni * 8 + 2 * q;
                __half2 h2 = __floats2half2_rn(acc[ni][hm * 2 + 0] + bv[ni].x,
                                               acc[ni][hm * 2 + 1] + bv[ni].y);
                uint32_t off = (uint32_t)(row * 256 + ((col * 2) ^ ((row & 7) << 4)));
                *reinterpret_cast<__half2*>(sOut + off) = h2;
            }
        }
        __syncthreads();
        const int r0 = t * 64;
        #pragma unroll
        for (int i = tid; i < 1024; i += 256) {
            int r = i >> 4, ch = i & 15;
            uint32_t off = (uint32_t)(r * 256 + ((ch * 16) ^ ((r & 7) << 4)));
            uint4 vv = *reinterpret_cast<uint4*>(sOut + off);
            int rr = r0 + r;
            if (rr < nrows)
                *reinterpret_cast<uint4*>(
                    reinterpret_cast<char*>(Out) + (size_t)rr * 256 + ch * 16) = vv;
        }
    }
}

// ---------------- Edge pass (fp16 U/V, L2-bound; unchanged) ----------------
__device__ __forceinline__ bool detect64(const int* p) {
    return (p[1] | p[3] | p[5] | p[7]) == 0;
}
__device__ __forceinline__ long long ldidx(const void* p, bool i64, int e) {
    if (i64) return ((const long long*)p)[e];
    return (long long)((const int*)p)[e];
}

__global__ void __launch_bounds__(256)
edge_kernel(const void* __restrict__ rowp,
            const void* __restrict__ colp,
            const float* __restrict__ w2,
            const float* __restrict__ b2,
            float* __restrict__ out, int E)
{
    const bool r64 = detect64((const int*)rowp);
    const bool c64 = detect64((const int*)colp);
    const int lane = threadIdx.x & 31;
    const int warp = (blockIdx.x * blockDim.x + threadIdx.x) >> 5;
    const int nw = (gridDim.x * blockDim.x) >> 5;
    const float4 wv = *reinterpret_cast<const float4*>(&w2[lane * 4]);
    const float bias = b2[0];

    for (int base = warp * 4; base < E; base += nw * 4) {
        long long r[4], c[4];
        #pragma unroll
        for (int i = 0; i < 4; i++) {
            int e = base + i;
            if (e >= E) e = E - 1;
            r[i] = ldidx(rowp, r64, e);
            c[i] = ldidx(colp, c64, e);
        }
        uint2 u[4], v[4];
        #pragma unroll
        for (int i = 0; i < 4; i++) {
            u[i] = *reinterpret_cast<const uint2*>(&gUh[r[i] * H + lane * 4]);
            v[i] = *reinterpret_cast<const uint2*>(&gVh[c[i] * H + lane * 4]);
        }
        #pragma unroll
        for (int i = 0; i < 4; i++) {
            float2 u01 = __half22float2(*reinterpret_cast<__half2*>(&u[i].x));
            float2 u23 = __half22float2(*reinterpret_cast<__half2*>(&u[i].y));
            float2 v01 = __half22float2(*reinterpret_cast<__half2*>(&v[i].x));
            float2 v23 = __half22float2(*reinterpret_cast<__half2*>(&v[i].y));
            float s = fmaxf(u01.x + v01.x, 0.f) * wv.x
                    + fmaxf(u01.y + v01.y, 0.f) * wv.y
                    + fmaxf(u23.x + v23.x, 0.f) * wv.z
                    + fmaxf(u23.y + v23.y, 0.f) * wv.w;
            #pragma unroll
            for (int off = 16; off; off >>= 1)
                s += __shfl_xor_sync(0xffffffffu, s, off);
            if (lane == 0 && base + i < E) out[base + i] = s + bias;
        }
    }
}

extern "C" void kernel_launch(void* const* d_in, const int* in_sizes, int n_in,
                              void* d_out, int out_size)
{
    const float* z_sotu  = (const float*)d_in[0];
    const float* z_taxon = (const float*)d_in[1];
    const void*  row     = d_in[2];
    const void*  col     = d_in[3];
    const float* w1      = (const float*)d_in[4];
    const float* b1      = (const float*)d_in[5];
    const float* w2      = (const float*)d_in[6];
    const float* b2      = (const float*)d_in[7];

    const int nsotu  = in_sizes[0] / H;
    const int ntaxon = in_sizes[1] / H;
    const int E      = in_sizes[2];

    const int smem_bytes = 112 * 1024 + 512;
    cudaFuncSetAttribute(mlp_mma_kernel,
                         cudaFuncAttributeMaxDynamicSharedMemorySize, smem_bytes);

    void* pU = nullptr;
    void* pV = nullptr;
    cudaGetSymbolAddress(&pU, gUh);
    cudaGetSymbolAddress(&pV, gVh);

    // Persistent grid: 148 CTAs split proportional to tile counts.
    const int tilesU = (nsotu + 63) / 64;
    const int tilesV = (ntaxon + 63) / 64;
    int gU_ctas = (int)((long long)tilesU * 148 / (tilesU + tilesV));
    if (gU_ctas < 1) gU_ctas = 1;
    if (gU_ctas > 147) gU_ctas = 147;
    const int gV_ctas = 148 - gU_ctas;

    prep_w_kernel<<<148, 256>>>(w1);
    mlp_mma_kernel<<<gU_ctas + gV_ctas, 256, smem_bytes>>>(
        z_sotu, z_taxon, b1, (__half*)pU, (__half*)pV, nsotu, ntaxon, gU_ctas, gV_ctas);
    edge_kernel<<<2048, 256>>>(row, col, w2, b2, (float*)d_out, E);
}

// round 8
// speedup vs baseline: 1.0057x; 1.0057x over previous
#include <cuda_runtime.h>
#include <cuda_fp16.h>
#include <cstdint>

#define H 128
#define MAX_SOTU 100000
#define MAX_TAXON 50000

// Scratch: factored first-layer outputs, stored fp16 (halves edge-pass traffic).
__device__ __half gUh[(size_t)MAX_SOTU * H];   // 25.6 MB
__device__ __half gVh[(size_t)MAX_TAXON * H];  // 12.8 MB
// Pre-swizzled fp16 hi/lo SMEM images of the two W1 halves, layout [n][k] with
// XOR swizzle (2k)^((n&7)<<4) on the byte offset within each 256B row.
__device__ __align__(16) unsigned short gBhi[2][128 * 128];
__device__ __align__(16) unsigned short gBlo[2][128 * 128];

__device__ __forceinline__ uint32_t smem_u32(const void* p) {
    uint32_t a;
    asm("{ .reg .u64 t; cvta.to.shared.u64 t, %1; cvt.u32.u64 %0, t; }" : "=r"(a) : "l"(p));
    return a;
}
__device__ __forceinline__ void ldsm4(uint32_t& r0, uint32_t& r1, uint32_t& r2,
                                      uint32_t& r3, uint32_t addr) {
    asm volatile("ldmatrix.sync.aligned.m8n8.x4.shared.b16 {%0,%1,%2,%3}, [%4];"
                 : "=r"(r0), "=r"(r1), "=r"(r2), "=r"(r3) : "r"(addr));
}
__device__ __forceinline__ void mma16816(float* c, const uint32_t* a, const uint32_t* b) {
    asm volatile(
        "mma.sync.aligned.m16n8k16.row.col.f32.f16.f16.f32 "
        "{%0,%1,%2,%3}, {%4,%5,%6,%7}, {%8,%9}, {%0,%1,%2,%3};"
        : "+f"(c[0]), "+f"(c[1]), "+f"(c[2]), "+f"(c[3])
        : "r"(a[0]), "r"(a[1]), "r"(a[2]), "r"(a[3]), "r"(b[0]), "r"(b[1]));
}
__device__ __forceinline__ void cp16(uint32_t dst, const void* src) {
    asm volatile("cp.async.cg.shared.global [%0], [%1], 16;" :: "r"(dst), "l"(src));
}
#define CP_COMMIT() asm volatile("cp.async.commit_group;" ::: "memory")
#define CP_WAIT0()  asm volatile("cp.async.wait_group 0;" ::: "memory")

__device__ __forceinline__ unsigned short h_bits(__half h) {
    return *reinterpret_cast<unsigned short*>(&h);
}
// Byte offset of element (r, k) in a 128-wide fp16 tile: 256B rows, XOR swizzle.
__device__ __forceinline__ uint32_t swz(int r, int k) {
    return (uint32_t)(r * 256 + ((k * 2) ^ ((r & 7) << 4)));
}

// ---------------- Prep: W1 halves -> pre-swizzled fp16 hi/lo images ----------------
__global__ void prep_w_kernel(const float* __restrict__ w1) {
    int stride = gridDim.x * blockDim.x;
    for (int idx = blockIdx.x * blockDim.x + threadIdx.x; idx < 2 * 128 * 128; idx += stride) {
        int half_id = idx >> 14;
        int e = idx & 16383;
        int o = e >> 7, k = e & 127;   // o = output col (n), k = input channel
        float x = w1[o * 256 + half_id * 128 + k];
        __half h = __float2half_rn(x);
        __half l = __float2half_rn(x - __half2float(h));
        uint32_t sw = swz(o, k) >> 1;
        gBhi[half_id][sw] = h_bits(h);
        gBlo[half_id][sw] = h_bits(l);
    }
}

// ---------------- Persistent first layer on HMMA: Out = Z @ W1half^T (+b1) ----------------
// Grid = NCTA persistent CTAs. CTAs [0, gU) stride over U tiles, rest over V tiles.
// Per CTA: B hi/lo loaded once; loop over 64-row tiles with software pipeline:
//   LDG A(t+1) -> regs | MMA(t) from smem | convert+STS A(t+1) | staged fp16 epilogue(t).
// SMEM: Bhi 32K | Blo 32K | A buf0 16K | A buf1 16K | sOut 16K = 112 KB.
__global__ void __launch_bounds__(256, 1)
mlp_mma_kernel(const float* __restrict__ zU, const float* __restrict__ zV,
               const float* __restrict__ b1,
               __half* __restrict__ outU, __half* __restrict__ outV,
               int nU, int nV, int gU_ctas, int gV_ctas)
{
    extern __shared__ char raw[];
    char* base = (char*)(((uintptr_t)raw + 255) & ~(uintptr_t)255);
    const uint32_t sb = smem_u32(base);
    const uint32_t offBhi = 0, offBlo = 32 * 1024;
    const uint32_t offA[2] = { 64u * 1024u, 80u * 1024u };
    char* sOut = base + 96 * 1024;

    const int tid = threadIdx.x;
    const int bx = blockIdx.x;

    const float* Z;
    __half* Out;
    int nrows, half_id, addBias, nCtas, ctaIdx;
    if (bx < gU_ctas) {
        Z = zU; Out = outU; nrows = nU; half_id = 0; addBias = 1;
        nCtas = gU_ctas; ctaIdx = bx;
    } else {
        Z = zV; Out = outV; nrows = nV; half_id = 1; addBias = 0;
        nCtas = gV_ctas; ctaIdx = bx - gU_ctas;
    }
    const int nTiles = (nrows + 63) / 64;

    // B tiles via cp.async, once per CTA.
    {
        const char* bh = reinterpret_cast<const char*>(gBhi[half_id]);
        const char* bl = reinterpret_cast<const char*>(gBlo[half_id]);
        #pragma unroll
        for (int i = 0; i < 8; i++) {
            int off = (tid + i * 256) * 16;
            cp16(sb + offBhi + off, bh + off);
            cp16(sb + offBlo + off, bl + off);
        }
        CP_COMMIT();
    }

    // Per-thread A-tile element coords: 8 float4 quads (64 rows x 32 quads / 256 thr).
    int a_r[8], a_kq[8];
    #pragma unroll
    for (int j = 0; j < 8; j++) {
        int i = tid + j * 256;
        a_r[j] = i >> 5; a_kq[j] = i & 31;
    }

    float4 vreg[8];
    auto ldgA = [&](int r0) {
        #pragma unroll
        for (int j = 0; j < 8; j++) {
            int rr = r0 + a_r[j];
            vreg[j] = (rr < nrows)
                ? *reinterpret_cast<const float4*>(&Z[(size_t)rr * H + a_kq[j] * 4])
                : make_float4(0.f, 0.f, 0.f, 0.f);
        }
    };
    auto stsA = [&](uint32_t bufOff) {
        #pragma unroll
        for (int j = 0; j < 8; j++) {
            uint32_t sw = swz(a_r[j], a_kq[j] * 4);
            char* p = base + bufOff + sw;
            *reinterpret_cast<__half2*>(p)     = __floats2half2_rn(vreg[j].x, vreg[j].y);
            *reinterpret_cast<__half2*>(p + 4) = __floats2half2_rn(vreg[j].z, vreg[j].w);
        }
    };

    const int w = tid >> 5, lane = tid & 31;
    const int mb = (w & 3) * 16;     // warp M origin
    const int nb = (w >> 2) * 64;    // warp N origin
    const int a_row = mb + (lane & 15);
    const int a_kof = (lane >> 4) * 8;
    const int b_row = nb + (lane >> 4) * 8 + (lane & 7);
    const int b_kof = ((lane >> 3) & 1) * 8;
    const int g = lane >> 2, q = lane & 3;

    float2 bv[8];
    #pragma unroll
    for (int ni = 0; ni < 8; ni++) {
        int col = nb + ni * 8 + 2 * q;
        bv[ni] = addBias ? *reinterpret_cast<const float2*>(&b1[col])
                         : make_float2(0.f, 0.f);
    }

    // Preload first tile.
    int t = ctaIdx;
    if (t >= nTiles) { CP_WAIT0(); return; }
    ldgA(t * 64);
    stsA(offA[0]);
    CP_WAIT0();
    __syncthreads();

    int bufc = 0;
    for (; t < nTiles; t += nCtas, bufc ^= 1) {
        const int tn = t + nCtas;
        const bool hasNext = tn < nTiles;
        if (hasNext) ldgA(tn * 64);

        float acc[8][4];
        #pragma unroll
        for (int ni = 0; ni < 8; ni++)
            #pragma unroll
            for (int qq = 0; qq < 4; qq++) acc[ni][qq] = 0.f;

        // 16 iters = 2 passes (Bhi, Blo) x 8 k-steps, fragment double-buffered.
        const uint32_t Abase = sb + offA[bufc];
        uint32_t a[2][4], b[2][8][2];
        auto load_frags = [&](int buf, int it) {
            int pass = it >> 3, k0 = (it & 7) * 16;
            uint32_t Bbase = sb + (pass ? offBlo : offBhi);
            ldsm4(a[buf][0], a[buf][1], a[buf][2], a[buf][3],
                  Abase + swz(a_row, k0 + a_kof));
            #pragma unroll
            for (int nj = 0; nj < 4; nj++)
                ldsm4(b[buf][2 * nj][0], b[buf][2 * nj][1],
                      b[buf][2 * nj + 1][0], b[buf][2 * nj + 1][1],
                      Bbase + swz(b_row + nj * 16, k0 + b_kof));
        };
        load_frags(0, 0);
        #pragma unroll
        for (int it = 0; it < 16; it++) {
            int cur = it & 1;
            if (it < 15) load_frags(cur ^ 1, it + 1);
            #pragma unroll
            for (int ni = 0; ni < 8; ni++)
                mma16816(acc[ni], a[cur], b[cur][ni]);
        }

        if (hasNext) stsA(offA[bufc ^ 1]);

        // Epilogue: acc -> sOut (swizzled fp16), then coalesced uint4 stores.
        __syncthreads();   // prior STG reads of sOut done; STS of next A visible next iter
        #pragma unroll
        for (int hm = 0; hm < 2; hm++) {
            int row = mb + hm * 8 + g;
            #pragma unroll
            for (int ni = 0; ni < 8; ni++) {
                int col = nb + ni * 8 + 2 * q;
                __half2 h2 = __floats2half2_rn(acc[ni][hm * 2 + 0] + bv[ni].x,
                                               acc[ni][hm * 2 + 1] + bv[ni].y);
                uint32_t off = (uint32_t)(row * 256 + ((col * 2) ^ ((row & 7) << 4)));
                *reinterpret_cast<__half2*>(sOut + off) = h2;
            }
        }
        __syncthreads();
        const int r0 = t * 64;
        #pragma unroll
        for (int i = tid; i < 1024; i += 256) {
            int r = i >> 4, ch = i & 15;
            uint32_t off = (uint32_t)(r * 256 + ((ch * 16) ^ ((r & 7) << 4)));
            uint4 vv = *reinterpret_cast<uint4*>(sOut + off);
            int rr = r0 + r;
            if (rr < nrows)
                *reinterpret_cast<uint4*>(
                    reinterpret_cast<char*>(Out) + (size_t)rr * 256 + ch * 16) = vv;
        }
    }
}

// ---------------- Edge pass (fp16 U/V, L2-bound; unchanged) ----------------
__device__ __forceinline__ bool detect64(const int* p) {
    return (p[1] | p[3] | p[5] | p[7]) == 0;
}
__device__ __forceinline__ long long ldidx(const void* p, bool i64, int e) {
    if (i64) return ((const long long*)p)[e];
    return (long long)((const int*)p)[e];
}

__global__ void __launch_bounds__(256)
edge_kernel(const void* __restrict__ rowp,
            const void* __restrict__ colp,
            const float* __restrict__ w2,
            const float* __restrict__ b2,
            float* __restrict__ out, int E)
{
    const bool r64 = detect64((const int*)rowp);
    const bool c64 = detect64((const int*)colp);
    const int lane = threadIdx.x & 31;
    const int warp = (blockIdx.x * blockDim.x + threadIdx.x) >> 5;
    const int nw = (gridDim.x * blockDim.x) >> 5;
    const float4 wv = *reinterpret_cast<const float4*>(&w2[lane * 4]);
    const float bias = b2[0];

    for (int base = warp * 4; base < E; base += nw * 4) {
        long long r[4], c[4];
        #pragma unroll
        for (int i = 0; i < 4; i++) {
            int e = base + i;
            if (e >= E) e = E - 1;
            r[i] = ldidx(rowp, r64, e);
            c[i] = ldidx(colp, c64, e);
        }
        uint2 u[4], v[4];
        #pragma unroll
        for (int i = 0; i < 4; i++) {
            u[i] = *reinterpret_cast<const uint2*>(&gUh[r[i] * H + lane * 4]);
            v[i] = *reinterpret_cast<const uint2*>(&gVh[c[i] * H + lane * 4]);
        }
        #pragma unroll
        for (int i = 0; i < 4; i++) {
            float2 u01 = __half22float2(*reinterpret_cast<__half2*>(&u[i].x));
            float2 u23 = __half22float2(*reinterpret_cast<__half2*>(&u[i].y));
            float2 v01 = __half22float2(*reinterpret_cast<__half2*>(&v[i].x));
            float2 v23 = __half22float2(*reinterpret_cast<__half2*>(&v[i].y));
            float s = fmaxf(u01.x + v01.x, 0.f) * wv.x
                    + fmaxf(u01.y + v01.y, 0.f) * wv.y
                    + fmaxf(u23.x + v23.x, 0.f) * wv.z
                    + fmaxf(u23.y + v23.y, 0.f) * wv.w;
            #pragma unroll
            for (int off = 16; off; off >>= 1)
                s += __shfl_xor_sync(0xffffffffu, s, off);
            if (lane == 0 && base + i < E) out[base + i] = s + bias;
        }
    }
}

extern "C" void kernel_launch(void* const* d_in, const int* in_sizes, int n_in,
                              void* d_out, int out_size)
{
    const float* z_sotu  = (const float*)d_in[0];
    const float* z_taxon = (const float*)d_in[1];
    const void*  row     = d_in[2];
    const void*  col     = d_in[3];
    const float* w1      = (const float*)d_in[4];
    const float* b1      = (const float*)d_in[5];
    const float* w2      = (const float*)d_in[6];
    const float* b2      = (const float*)d_in[7];

    const int nsotu  = in_sizes[0] / H;
    const int ntaxon = in_sizes[1] / H;
    const int E      = in_sizes[2];

    const int smem_bytes = 112 * 1024 + 512;
    cudaFuncSetAttribute(mlp_mma_kernel,
                         cudaFuncAttributeMaxDynamicSharedMemorySize, smem_bytes);

    void* pU = nullptr;
    void* pV = nullptr;
    cudaGetSymbolAddress(&pU, gUh);
    cudaGetSymbolAddress(&pV, gVh);

    // Persistent grid: 148 CTAs split proportional to tile counts.
    const int tilesU = (nsotu + 63) / 64;
    const int tilesV = (ntaxon + 63) / 64;
    int gU_ctas = (int)((long long)tilesU * 148 / (tilesU + tilesV));
    if (gU_ctas < 1) gU_ctas = 1;
    if (gU_ctas > 147) gU_ctas = 147;
    const int gV_ctas = 148 - gU_ctas;

    prep_w_kernel<<<148, 256>>>(w1);
    mlp_mma_kernel<<<gU_ctas + gV_ctas, 256, smem_bytes>>>(
        z_sotu, z_taxon, b1, (__half*)pU, (__half*)pV, nsotu, ntaxon, gU_ctas, gV_ctas);
    edge_kernel<<<2048, 256>>>(row, col, w2, b2, (float*)d_out, E);
}